// round 16
// baseline (speedup 1.0000x reference)
#include <cuda_runtime.h>
#include <cuda_fp16.h>
#include <cstdint>

// ---------------- problem constants ----------------
#define NN   50000
#define EE   800000
#define FIN  128
#define HH   4
#define CC1  64
#define CC2  32
#define NEG_SLOPE 0.2f
#define EPSV 1e-16f

#define SCAN_CHUNK 256
#define NB ((NN + SCAN_CHUNK - 1) / SCAN_CHUNK)   // 196

// ---------------- device scratch (no allocs allowed) ----------------
__device__ __half g_feat[NN * HH * CC1];   // h per layer, fp16
__device__ __half g_hmid[NN * CC1];        // layer1 output, fp16 (input to layer2 MMA)
__device__ float g_as[NN * HH];
__device__ float g_ad[NN * HH];
__device__ int   g_deg[NN];
__device__ int   g_rowptr[NN + 1];
__device__ int   g_cursor[NN];
__device__ int   g_csr_src[EE];
__device__ int   g_partial[NB];

// ---------------- CSR build kernels ----------------
// dtype detect: first 8 words as int64 all in [0,NN) => int64 (false-pos ~(1/NN)^8).
__device__ __forceinline__ bool ei_is64(const void* ei_raw) {
    const long long* p64 = (const long long*)ei_raw;
    bool is64 = true;
#pragma unroll
    for (int k = 0; k < 8; k++) {
        long long v = p64[k];
        if (v < 0 || v >= NN) { is64 = false; break; }
    }
    return is64;
}

// Histogram of in-degrees (reads only the dst half of edge_index).
__global__ void hist_kernel(const void* __restrict__ ei_raw, int* __restrict__ deg) {
    bool is64 = ei_is64(ei_raw);
    int i = blockIdx.x * blockDim.x + threadIdx.x;
    int stride = gridDim.x * blockDim.x;
    if (is64) {
        const long long* p64 = (const long long*)ei_raw;
        for (; i < EE; i += stride) atomicAdd(&deg[(int)p64[EE + i]], 1);
    } else {
        const int* p32 = (const int*)ei_raw;
        for (; i < EE; i += stride) atomicAdd(&deg[p32[EE + i]], 1);
    }
}

// Phase A: per-chunk sums.
__global__ void scan_partials_kernel(const int* __restrict__ deg, int* __restrict__ partial) {
    __shared__ int sm[SCAN_CHUNK];
    int b = blockIdx.x, t = threadIdx.x;
    int i = b * SCAN_CHUNK + t;
    sm[t] = (i < NN) ? deg[i] : 0;
    __syncthreads();
#pragma unroll
    for (int off = 128; off; off >>= 1) {
        if (t < off) sm[t] += sm[t + off];
        __syncthreads();
    }
    if (t == 0) partial[b] = sm[0];
}

// Phase B (merged): each block scans the partials itself for its offset, then
// does the local chunk scan -> rowptr/cursor.
__global__ void scan_final_kernel(const int* __restrict__ deg,
                                  const int* __restrict__ partial,
                                  int* __restrict__ rowptr, int* __restrict__ cursor) {
    __shared__ int sp[256];
    __shared__ int sm[SCAN_CHUNK];
    int b = blockIdx.x, t = threadIdx.x;

    // inclusive scan of partials in smem, then convert to exclusive
    int pv = (t < NB) ? partial[t] : 0;
    sp[t] = pv;
    __syncthreads();
#pragma unroll
    for (int off = 1; off < 256; off <<= 1) {
        int x = (t >= off) ? sp[t - off] : 0;
        __syncthreads();
        sp[t] += x;
        __syncthreads();
    }
    int incl = sp[t];
    __syncthreads();
    sp[t] = incl - pv;      // exclusive prefix
    __syncthreads();
    int blockOff = sp[b];

    // local chunk scan
    int i = b * SCAN_CHUNK + t;
    int v = (i < NN) ? deg[i] : 0;
    sm[t] = v;
    __syncthreads();
#pragma unroll
    for (int off = 1; off < SCAN_CHUNK; off <<= 1) {
        int x = (t >= off) ? sm[t - off] : 0;
        __syncthreads();
        sm[t] += x;
        __syncthreads();
    }
    if (i < NN) {
        int excl = sm[t] - v + blockOff;
        rowptr[i] = excl;
        cursor[i] = excl;
    }
    if (b == 0 && t == 0) rowptr[NN] = EE;
}

// Scatter edge src ids into CSR slots grouped by dst, decoding ei directly.
__global__ void fill_csr_kernel(const void* __restrict__ ei_raw,
                                int* __restrict__ cursor, int* __restrict__ csr_src) {
    bool is64 = ei_is64(ei_raw);
    int i = blockIdx.x * blockDim.x + threadIdx.x;
    int stride = gridDim.x * blockDim.x;
    if (is64) {
        const long long* p64 = (const long long*)ei_raw;
        for (; i < EE; i += stride) {
            int s = (int)p64[i], d = (int)p64[EE + i];
            csr_src[atomicAdd(&cursor[d], 1)] = s;
        }
    } else {
        const int* p32 = (const int*)ei_raw;
        for (; i < EE; i += stride) {
            int s = p32[i], d = p32[EE + i];
            csr_src[atomicAdd(&cursor[d], 1)] = s;
        }
    }
}

// ---------------- helpers ----------------
__device__ __forceinline__ uint32_t pack_h2(float a, float b) {
    __half2 h = __float22half2_rn(make_float2(a, b));
    return *reinterpret_cast<uint32_t*>(&h);
}

// ---------------- tensor-core GEMM (mma.sync m16n8k16, fp16 in / fp32 acc) ----------------
// C[n, M=HH*C] = A[n,K] @ B[K,M].  Block tile 128x64, 8 warps (2 M x 4 N).
// A16: A is fp16 (layer2 hmid); else fp32 (layer1 x), converted in-register.
// B is always fp32 (W1/W2), converted in-register. Epilogue: acc -> smem h tile
// -> fp16 global store + fused attention dot products.
template <int K, int C, bool A16>
__global__ void __launch_bounds__(256) gemm_mma_kernel(
        const void* __restrict__ Ap, const float* __restrict__ Bf,
        __half* __restrict__ Cout, int n,
        const float* __restrict__ att_s, const float* __restrict__ att_d,
        float* __restrict__ as_o, float* __restrict__ ad_o) {
    constexpr int M = HH * C;
    constexpr int CPR = K / 8;                 // 16B (8-half) chunks per A row
    __shared__ __half As[128 * K];             // swizzled A tile; reused as h tile
    __shared__ __half Bs[K * 64];              // swizzled B tile

    const int tid = threadIdx.x;
    const int lane = tid & 31;
    const int warp = tid >> 5;
    const int mwarp = warp & 1;
    const int nwarp = warp >> 1;
    const int rowBase = blockIdx.y * 128;
    const int colBase = blockIdx.x * 64;

    // ---- load A tile (convert fp32 -> fp16 if needed; swizzle chunk ^= row&7) ----
    for (int idx = tid; idx < 128 * CPR; idx += 256) {
        int r = idx / CPR, c = idx % CPR;
        int rg = rowBase + r;
        uint4 v = make_uint4(0u, 0u, 0u, 0u);
        if (rg < n) {
            if (A16) {
                v = ((const uint4*)((const __half*)Ap + (size_t)rg * K))[c];
            } else {
                const float4* ap = (const float4*)((const float*)Ap + (size_t)rg * K + c * 8);
                float4 f0 = ap[0], f1 = ap[1];
                v = make_uint4(pack_h2(f0.x, f0.y), pack_h2(f0.z, f0.w),
                               pack_h2(f1.x, f1.y), pack_h2(f1.z, f1.w));
            }
        }
        ((uint4*)As)[r * CPR + (c ^ (r & 7))] = v;
    }
    // ---- load B tile (fp32 -> fp16) ----
    for (int idx = tid; idx < K * 8; idx += 256) {
        int r = idx >> 3, c = idx & 7;
        const float4* bp = (const float4*)(Bf + (size_t)r * M + colBase + c * 8);
        float4 f0 = bp[0], f1 = bp[1];
        uint4 v = make_uint4(pack_h2(f0.x, f0.y), pack_h2(f0.z, f0.w),
                             pack_h2(f1.x, f1.y), pack_h2(f1.z, f1.w));
        ((uint4*)Bs)[r * 8 + (c ^ (r & 7))] = v;
    }
    __syncthreads();

    uint32_t asbase = (uint32_t)__cvta_generic_to_shared(As);
    uint32_t bsbase = (uint32_t)__cvta_generic_to_shared(Bs);

    float acc[4][2][4];
#pragma unroll
    for (int mt = 0; mt < 4; mt++)
#pragma unroll
        for (int nt = 0; nt < 2; nt++)
#pragma unroll
            for (int q = 0; q < 4; q++) acc[mt][nt][q] = 0.f;

#pragma unroll
    for (int ks = 0; ks < K / 16; ks++) {
        uint32_t af[4][4];
#pragma unroll
        for (int mt = 0; mt < 4; mt++) {
            int m0 = mwarp * 64 + mt * 16;
            int r = m0 + (lane & 7) + (lane & 8);
            int chunk = ks * 2 + (lane >> 4);
            int swz = chunk ^ (r & 7);
            uint32_t addr = asbase + (uint32_t)(r * K + swz * 8) * 2u;
            asm volatile("ldmatrix.sync.aligned.m8n8.x4.shared.b16 {%0,%1,%2,%3}, [%4];"
                         : "=r"(af[mt][0]), "=r"(af[mt][1]), "=r"(af[mt][2]), "=r"(af[mt][3])
                         : "r"(addr));
        }
        uint32_t bf[2][2];
#pragma unroll
        for (int nt = 0; nt < 2; nt++) {
            int n0 = nwarp * 16 + nt * 8;
            int l = lane & 15;
            int r = ks * 16 + (l & 7) + (l & 8);
            int swz = (n0 >> 3) ^ (r & 7);
            uint32_t addr = bsbase + (uint32_t)(r * 64 + swz * 8) * 2u;
            asm volatile("ldmatrix.sync.aligned.m8n8.x2.trans.shared.b16 {%0,%1}, [%2];"
                         : "=r"(bf[nt][0]), "=r"(bf[nt][1])
                         : "r"(addr));
        }
#pragma unroll
        for (int mt = 0; mt < 4; mt++)
#pragma unroll
            for (int nt = 0; nt < 2; nt++) {
                asm volatile(
                    "mma.sync.aligned.m16n8k16.row.col.f32.f16.f16.f32 "
                    "{%0,%1,%2,%3}, {%4,%5,%6,%7}, {%8,%9}, {%0,%1,%2,%3};"
                    : "+f"(acc[mt][nt][0]), "+f"(acc[mt][nt][1]),
                      "+f"(acc[mt][nt][2]), "+f"(acc[mt][nt][3])
                    : "r"(af[mt][0]), "r"(af[mt][1]), "r"(af[mt][2]), "r"(af[mt][3]),
                      "r"(bf[nt][0]), "r"(bf[nt][1]));
            }
    }

    __syncthreads();
    __half* htile = As;              // reuse as [128][64] h tile
    {
        int gid = lane >> 2, tig = lane & 3;
#pragma unroll
        for (int mt = 0; mt < 4; mt++)
#pragma unroll
            for (int nt = 0; nt < 2; nt++) {
                int r0 = mwarp * 64 + mt * 16 + gid;
                int c0 = nwarp * 16 + nt * 8 + tig * 2;
                *(__half2*)(htile + r0 * 64 + c0) =
                    __float22half2_rn(make_float2(acc[mt][nt][0], acc[mt][nt][1]));
                *(__half2*)(htile + (r0 + 8) * 64 + c0) =
                    __float22half2_rn(make_float2(acc[mt][nt][2], acc[mt][nt][3]));
            }
    }
    __syncthreads();

    {
        int r = tid >> 1, hf = tid & 1;
        int rg = rowBase + r;
        int head = (C == 64) ? blockIdx.x : (blockIdx.x * 2 + hf);
        const __half2* hp = (const __half2*)(htile + r * 64 + hf * 32);
        const float* sa = att_s + head * C + ((C == 64) ? hf * 32 : 0);
        const float* da = att_d + head * C + ((C == 64) ? hf * 32 : 0);
        float ps = 0.f, pd = 0.f;
#pragma unroll
        for (int j = 0; j < 16; j++) {
            float2 u = __half22float2(hp[j]);
            ps += u.x * sa[2 * j] + u.y * sa[2 * j + 1];
            pd += u.x * da[2 * j] + u.y * da[2 * j + 1];
        }
        if (C == 64) {
            ps += __shfl_xor_sync(0xffffffffu, ps, 1);
            pd += __shfl_xor_sync(0xffffffffu, pd, 1);
        }
        if (rg < n) {
            const uint4* srcp = (const uint4*)(htile + r * 64 + hf * 32);
            uint4* dstp = (uint4*)(Cout + (size_t)rg * M + colBase + hf * 32);
#pragma unroll
            for (int q = 0; q < 4; q++) dstp[q] = srcp[q];
            if (C == 32 || hf == 0) {
                as_o[rg * HH + head] = ps;
                ad_o[rg * HH + head] = pd;
            }
        }
    }
}

// ---------------- fused pull-mode GAT aggregation (fp16 gather, unroll 8/4/1) ----------------
// One block per destination node; NT = HH*C/2 threads; thread t owns one half2.
// All accumulation in fp32. HOUT: fp16 output (layer1 feeds layer2 MMA).
template <int C, bool HOUT>
__global__ void __launch_bounds__(HH * C / 2) gat_aggregate_kernel(
        const int* __restrict__ rowptr,
        const int* __restrict__ csr_src,
        const float* __restrict__ as_i,
        const float* __restrict__ ad_i,
        const __half2* __restrict__ feat,   // [N, HH*C/2]
        const float* __restrict__ bias,
        void* __restrict__ outp, int do_relu) {
    constexpr int NT = HH * C / 2;
    __shared__ float sm[HH * C];
    const int node = blockIdx.x;
    const int t = threadIdx.x;
    const int head = (2 * t) / C;
    const float adh = ad_i[node * HH + head];
    int beg = rowptr[node], end = rowptr[node + 1];
    float acc0 = 0.f, acc1 = 0.f, denom = 0.f;

    int e = beg;
    for (; e + 8 <= end; e += 8) {
        int s[8]; float a[8]; __half2 u[8];
#pragma unroll
        for (int q = 0; q < 8; q++) s[q] = __ldg(&csr_src[e + q]);
#pragma unroll
        for (int q = 0; q < 8; q++) u[q] = feat[(size_t)s[q] * NT + t];
#pragma unroll
        for (int q = 0; q < 8; q++) a[q] = __ldg(&as_i[s[q] * HH + head]);
#pragma unroll
        for (int q = 0; q < 8; q++) {
            float eq = a[q] + adh; eq = eq > 0.f ? eq : NEG_SLOPE * eq;
            float xq = __expf(eq);
            float2 uf = __half22float2(u[q]);
            denom += xq;
            acc0 += xq * uf.x;
            acc1 += xq * uf.y;
        }
    }
    for (; e + 4 <= end; e += 4) {
        int s[4]; float a[4]; __half2 u[4];
#pragma unroll
        for (int q = 0; q < 4; q++) s[q] = __ldg(&csr_src[e + q]);
#pragma unroll
        for (int q = 0; q < 4; q++) u[q] = feat[(size_t)s[q] * NT + t];
#pragma unroll
        for (int q = 0; q < 4; q++) a[q] = __ldg(&as_i[s[q] * HH + head]);
#pragma unroll
        for (int q = 0; q < 4; q++) {
            float eq = a[q] + adh; eq = eq > 0.f ? eq : NEG_SLOPE * eq;
            float xq = __expf(eq);
            float2 uf = __half22float2(u[q]);
            denom += xq;
            acc0 += xq * uf.x;
            acc1 += xq * uf.y;
        }
    }
    for (; e < end; e++) {
        int s0 = __ldg(&csr_src[e]);
        float a0 = __ldg(&as_i[s0 * HH + head]);
        float2 u0 = __half22float2(feat[(size_t)s0 * NT + t]);
        float e0 = a0 + adh; e0 = e0 > 0.f ? e0 : NEG_SLOPE * e0;
        float x0 = __expf(e0);
        denom += x0;
        acc0 += x0 * u0.x;
        acc1 += x0 * u0.y;
    }

    float inv = 1.f / (denom + EPSV);
    sm[2 * t]     = acc0 * inv;
    sm[2 * t + 1] = acc1 * inv;
    __syncthreads();
    if (t < C) {
        float v = 0.25f * (sm[t] + sm[C + t] + sm[2 * C + t] + sm[3 * C + t]) + bias[t];
        if (do_relu) v = fmaxf(v, 0.f);
        if (HOUT) ((__half*)outp)[(size_t)node * C + t] = __float2half(v);
        else      ((float*)outp)[(size_t)node * C + t] = v;
    }
}

// ---------------- host launcher ----------------
extern "C" void kernel_launch(void* const* d_in, const int* in_sizes, int n_in,
                              void* d_out, int out_size) {
    const float* x   = (const float*)d_in[0];
    const void*  ei  = d_in[1];
    const float* W1  = (const float*)d_in[2];
    const float* as1 = (const float*)d_in[3];
    const float* ad1 = (const float*)d_in[4];
    const float* b1  = (const float*)d_in[5];
    const float* W2  = (const float*)d_in[6];
    const float* as2 = (const float*)d_in[7];
    const float* ad2 = (const float*)d_in[8];
    const float* b2  = (const float*)d_in[9];
    float* out = (float*)d_out;

    __half *feat, *hmid;
    float *asb, *adb;
    int *deg, *rowptr, *cursor, *csr, *partial;
    cudaGetSymbolAddress((void**)&feat,    g_feat);
    cudaGetSymbolAddress((void**)&hmid,    g_hmid);
    cudaGetSymbolAddress((void**)&asb,     g_as);
    cudaGetSymbolAddress((void**)&adb,     g_ad);
    cudaGetSymbolAddress((void**)&deg,     g_deg);
    cudaGetSymbolAddress((void**)&rowptr,  g_rowptr);
    cudaGetSymbolAddress((void**)&cursor,  g_cursor);
    cudaGetSymbolAddress((void**)&csr,     g_csr_src);
    cudaGetSymbolAddress((void**)&partial, g_partial);

    // One-time resources (created on first, uncaptured correctness call; reused
    // in graph capture — same work every call, fully deterministic).
    static cudaStream_t sCsr = nullptr;
    static cudaEvent_t evFork = nullptr, evCsr = nullptr;
    if (!sCsr) {
        cudaStreamCreateWithFlags(&sCsr, cudaStreamNonBlocking);
        cudaEventCreateWithFlags(&evFork, cudaEventDisableTiming);
        cudaEventCreateWithFlags(&evCsr, cudaEventDisableTiming);
    }

    const int rowBlocks = (NN + 127) / 128;   // 391

    // ---- fork: GEMM1 on main stream, CSR build on sCsr ----
    cudaEventRecord(evFork, 0);
    cudaStreamWaitEvent(sCsr, evFork, 0);

    // Main branch: GEMM1 (fp32 x / W1 converted in-kernel)
    gemm_mma_kernel<FIN, CC1, false><<<dim3(HH * CC1 / 64, rowBlocks), 256>>>(
        x, W1, feat, NN, as1, ad1, asb, adb);

    // CSR branch (independent of features/weights)
    cudaMemsetAsync(deg, 0, NN * sizeof(int), sCsr);
    hist_kernel<<<1024, 256, 0, sCsr>>>(ei, deg);
    scan_partials_kernel<<<NB, SCAN_CHUNK, 0, sCsr>>>(deg, partial);
    scan_final_kernel<<<NB, SCAN_CHUNK, 0, sCsr>>>(deg, partial, rowptr, cursor);
    fill_csr_kernel<<<512, 256, 0, sCsr>>>(ei, cursor, csr);
    cudaEventRecord(evCsr, sCsr);

    // ---- join: aggregation needs both GEMM1 outputs and the CSR ----
    cudaStreamWaitEvent(0, evCsr, 0);

    gat_aggregate_kernel<CC1, true><<<NN, HH * CC1 / 2>>>(
        rowptr, csr, asb, adb, (const __half2*)feat, b1, hmid, 1);

    // ---- layer 2 (A = fp16 hmid, B = fp32 W2 converted in-kernel) ----
    gemm_mma_kernel<CC1, CC2, true><<<dim3(HH * CC2 / 64, rowBlocks), 256>>>(
        hmid, W2, feat, NN, as2, ad2, asb, adb);
    gat_aggregate_kernel<CC2, false><<<NN, HH * CC2 / 2>>>(
        rowptr, csr, asb, adb, (const __half2*)feat, b2, out, 0);
}

// round 17
// speedup vs baseline: 1.5331x; 1.5331x over previous
#include <cuda_runtime.h>
#include <cuda_fp16.h>
#include <cstdint>

// ---------------- problem constants ----------------
#define NN   50000
#define EE   800000
#define FIN  128
#define HH   4
#define CC1  64
#define CC2  32
#define NEG_SLOPE 0.2f
#define EPSV 1e-16f

#define SCAN_CHUNK 256
#define NB ((NN + SCAN_CHUNK - 1) / SCAN_CHUNK)   // 196

// ---------------- device scratch (no allocs allowed) ----------------
__device__ __align__(16) __half g_feat[NN * HH * CC1];   // h per layer, fp16
__device__ __align__(16) __half g_hmid[NN * CC1];        // layer1 output, fp16
__device__ float g_as[NN * HH];
__device__ float g_ad[NN * HH];
__device__ int   g_deg[NN];
__device__ int   g_rowptr[NN + 1];
__device__ int   g_cursor[NN];
__device__ int   g_csr_src[EE];
__device__ int   g_partial[NB];

// ---------------- CSR build kernels ----------------
// dtype detect: first 8 words as int64 all in [0,NN) => int64 (false-pos ~(1/NN)^8).
__device__ __forceinline__ bool ei_is64(const void* ei_raw) {
    const long long* p64 = (const long long*)ei_raw;
    bool is64 = true;
#pragma unroll
    for (int k = 0; k < 8; k++) {
        long long v = p64[k];
        if (v < 0 || v >= NN) { is64 = false; break; }
    }
    return is64;
}

// Histogram of in-degrees (reads only the dst half of edge_index).
__global__ void hist_kernel(const void* __restrict__ ei_raw, int* __restrict__ deg) {
    bool is64 = ei_is64(ei_raw);
    int i = blockIdx.x * blockDim.x + threadIdx.x;
    int stride = gridDim.x * blockDim.x;
    if (is64) {
        const long long* p64 = (const long long*)ei_raw;
        for (; i < EE; i += stride) atomicAdd(&deg[(int)p64[EE + i]], 1);
    } else {
        const int* p32 = (const int*)ei_raw;
        for (; i < EE; i += stride) atomicAdd(&deg[p32[EE + i]], 1);
    }
}

// Phase A: per-chunk sums.
__global__ void scan_partials_kernel(const int* __restrict__ deg, int* __restrict__ partial) {
    __shared__ int sm[SCAN_CHUNK];
    int b = blockIdx.x, t = threadIdx.x;
    int i = b * SCAN_CHUNK + t;
    sm[t] = (i < NN) ? deg[i] : 0;
    __syncthreads();
#pragma unroll
    for (int off = 128; off; off >>= 1) {
        if (t < off) sm[t] += sm[t + off];
        __syncthreads();
    }
    if (t == 0) partial[b] = sm[0];
}

// Phase B (merged): each block scans the partials itself for its offset, then
// does the local chunk scan -> rowptr/cursor.
__global__ void scan_final_kernel(const int* __restrict__ deg,
                                  const int* __restrict__ partial,
                                  int* __restrict__ rowptr, int* __restrict__ cursor) {
    __shared__ int sp[256];
    __shared__ int sm[SCAN_CHUNK];
    int b = blockIdx.x, t = threadIdx.x;

    int pv = (t < NB) ? partial[t] : 0;
    sp[t] = pv;
    __syncthreads();
#pragma unroll
    for (int off = 1; off < 256; off <<= 1) {
        int x = (t >= off) ? sp[t - off] : 0;
        __syncthreads();
        sp[t] += x;
        __syncthreads();
    }
    int incl = sp[t];
    __syncthreads();
    sp[t] = incl - pv;      // exclusive prefix
    __syncthreads();
    int blockOff = sp[b];

    int i = b * SCAN_CHUNK + t;
    int v = (i < NN) ? deg[i] : 0;
    sm[t] = v;
    __syncthreads();
#pragma unroll
    for (int off = 1; off < SCAN_CHUNK; off <<= 1) {
        int x = (t >= off) ? sm[t - off] : 0;
        __syncthreads();
        sm[t] += x;
        __syncthreads();
    }
    if (i < NN) {
        int excl = sm[t] - v + blockOff;
        rowptr[i] = excl;
        cursor[i] = excl;
    }
    if (b == 0 && t == 0) rowptr[NN] = EE;
}

// Scatter edge src ids into CSR slots grouped by dst, decoding ei directly.
__global__ void fill_csr_kernel(const void* __restrict__ ei_raw,
                                int* __restrict__ cursor, int* __restrict__ csr_src) {
    bool is64 = ei_is64(ei_raw);
    int i = blockIdx.x * blockDim.x + threadIdx.x;
    int stride = gridDim.x * blockDim.x;
    if (is64) {
        const long long* p64 = (const long long*)ei_raw;
        for (; i < EE; i += stride) {
            int s = (int)p64[i], d = (int)p64[EE + i];
            csr_src[atomicAdd(&cursor[d], 1)] = s;
        }
    } else {
        const int* p32 = (const int*)ei_raw;
        for (; i < EE; i += stride) {
            int s = p32[i], d = p32[EE + i];
            csr_src[atomicAdd(&cursor[d], 1)] = s;
        }
    }
}

// ---------------- helpers ----------------
__device__ __forceinline__ uint32_t pack_h2(float a, float b) {
    __half2 h = __float22half2_rn(make_float2(a, b));
    return *reinterpret_cast<uint32_t*>(&h);
}

// ---------------- tensor-core GEMM (mma.sync m16n8k16, fp16 in / fp32 acc) ----------------
// C[n, M=HH*C] = A[n,K] @ B[K,M].  Block tile 128x64, 8 warps (2 M x 4 N).
// A16: A is fp16 (layer2 hmid); else fp32 (layer1 x), converted in-register.
// B is always fp32 (W1/W2), converted in-register. Epilogue: acc -> smem h tile
// -> fp16 global store + fused attention dot products.
template <int K, int C, bool A16>
__global__ void __launch_bounds__(256) gemm_mma_kernel(
        const void* __restrict__ Ap, const float* __restrict__ Bf,
        __half* __restrict__ Cout, int n,
        const float* __restrict__ att_s, const float* __restrict__ att_d,
        float* __restrict__ as_o, float* __restrict__ ad_o) {
    constexpr int M = HH * C;
    constexpr int CPR = K / 8;                 // 16B (8-half) chunks per A row
    __shared__ __half As[128 * K];             // swizzled A tile; reused as h tile
    __shared__ __half Bs[K * 64];              // swizzled B tile

    const int tid = threadIdx.x;
    const int lane = tid & 31;
    const int warp = tid >> 5;
    const int mwarp = warp & 1;
    const int nwarp = warp >> 1;
    const int rowBase = blockIdx.y * 128;
    const int colBase = blockIdx.x * 64;

    for (int idx = tid; idx < 128 * CPR; idx += 256) {
        int r = idx / CPR, c = idx % CPR;
        int rg = rowBase + r;
        uint4 v = make_uint4(0u, 0u, 0u, 0u);
        if (rg < n) {
            if (A16) {
                v = ((const uint4*)((const __half*)Ap + (size_t)rg * K))[c];
            } else {
                const float4* ap = (const float4*)((const float*)Ap + (size_t)rg * K + c * 8);
                float4 f0 = ap[0], f1 = ap[1];
                v = make_uint4(pack_h2(f0.x, f0.y), pack_h2(f0.z, f0.w),
                               pack_h2(f1.x, f1.y), pack_h2(f1.z, f1.w));
            }
        }
        ((uint4*)As)[r * CPR + (c ^ (r & 7))] = v;
    }
    for (int idx = tid; idx < K * 8; idx += 256) {
        int r = idx >> 3, c = idx & 7;
        const float4* bp = (const float4*)(Bf + (size_t)r * M + colBase + c * 8);
        float4 f0 = bp[0], f1 = bp[1];
        uint4 v = make_uint4(pack_h2(f0.x, f0.y), pack_h2(f0.z, f0.w),
                             pack_h2(f1.x, f1.y), pack_h2(f1.z, f1.w));
        ((uint4*)Bs)[r * 8 + (c ^ (r & 7))] = v;
    }
    __syncthreads();

    uint32_t asbase = (uint32_t)__cvta_generic_to_shared(As);
    uint32_t bsbase = (uint32_t)__cvta_generic_to_shared(Bs);

    float acc[4][2][4];
#pragma unroll
    for (int mt = 0; mt < 4; mt++)
#pragma unroll
        for (int nt = 0; nt < 2; nt++)
#pragma unroll
            for (int q = 0; q < 4; q++) acc[mt][nt][q] = 0.f;

#pragma unroll
    for (int ks = 0; ks < K / 16; ks++) {
        uint32_t af[4][4];
#pragma unroll
        for (int mt = 0; mt < 4; mt++) {
            int m0 = mwarp * 64 + mt * 16;
            int r = m0 + (lane & 7) + (lane & 8);
            int chunk = ks * 2 + (lane >> 4);
            int swz = chunk ^ (r & 7);
            uint32_t addr = asbase + (uint32_t)(r * K + swz * 8) * 2u;
            asm volatile("ldmatrix.sync.aligned.m8n8.x4.shared.b16 {%0,%1,%2,%3}, [%4];"
                         : "=r"(af[mt][0]), "=r"(af[mt][1]), "=r"(af[mt][2]), "=r"(af[mt][3])
                         : "r"(addr));
        }
        uint32_t bf[2][2];
#pragma unroll
        for (int nt = 0; nt < 2; nt++) {
            int n0 = nwarp * 16 + nt * 8;
            int l = lane & 15;
            int r = ks * 16 + (l & 7) + (l & 8);
            int swz = (n0 >> 3) ^ (r & 7);
            uint32_t addr = bsbase + (uint32_t)(r * 64 + swz * 8) * 2u;
            asm volatile("ldmatrix.sync.aligned.m8n8.x2.trans.shared.b16 {%0,%1}, [%2];"
                         : "=r"(bf[nt][0]), "=r"(bf[nt][1])
                         : "r"(addr));
        }
#pragma unroll
        for (int mt = 0; mt < 4; mt++)
#pragma unroll
            for (int nt = 0; nt < 2; nt++) {
                asm volatile(
                    "mma.sync.aligned.m16n8k16.row.col.f32.f16.f16.f32 "
                    "{%0,%1,%2,%3}, {%4,%5,%6,%7}, {%8,%9}, {%0,%1,%2,%3};"
                    : "+f"(acc[mt][nt][0]), "+f"(acc[mt][nt][1]),
                      "+f"(acc[mt][nt][2]), "+f"(acc[mt][nt][3])
                    : "r"(af[mt][0]), "r"(af[mt][1]), "r"(af[mt][2]), "r"(af[mt][3]),
                      "r"(bf[nt][0]), "r"(bf[nt][1]));
            }
    }

    __syncthreads();
    __half* htile = As;              // reuse as [128][64] h tile
    {
        int gid = lane >> 2, tig = lane & 3;
#pragma unroll
        for (int mt = 0; mt < 4; mt++)
#pragma unroll
            for (int nt = 0; nt < 2; nt++) {
                int r0 = mwarp * 64 + mt * 16 + gid;
                int c0 = nwarp * 16 + nt * 8 + tig * 2;
                *(__half2*)(htile + r0 * 64 + c0) =
                    __float22half2_rn(make_float2(acc[mt][nt][0], acc[mt][nt][1]));
                *(__half2*)(htile + (r0 + 8) * 64 + c0) =
                    __float22half2_rn(make_float2(acc[mt][nt][2], acc[mt][nt][3]));
            }
    }
    __syncthreads();

    {
        int r = tid >> 1, hf = tid & 1;
        int rg = rowBase + r;
        int head = (C == 64) ? blockIdx.x : (blockIdx.x * 2 + hf);
        const __half2* hp = (const __half2*)(htile + r * 64 + hf * 32);
        const float* sa = att_s + head * C + ((C == 64) ? hf * 32 : 0);
        const float* da = att_d + head * C + ((C == 64) ? hf * 32 : 0);
        float ps = 0.f, pd = 0.f;
#pragma unroll
        for (int j = 0; j < 16; j++) {
            float2 u = __half22float2(hp[j]);
            ps += u.x * sa[2 * j] + u.y * sa[2 * j + 1];
            pd += u.x * da[2 * j] + u.y * da[2 * j + 1];
        }
        if (C == 64) {
            ps += __shfl_xor_sync(0xffffffffu, ps, 1);
            pd += __shfl_xor_sync(0xffffffffu, pd, 1);
        }
        if (rg < n) {
            const uint4* srcp = (const uint4*)(htile + r * 64 + hf * 32);
            uint4* dstp = (uint4*)(Cout + (size_t)rg * M + colBase + hf * 32);
#pragma unroll
            for (int q = 0; q < 4; q++) dstp[q] = srcp[q];
            if (C == 32 || hf == 0) {
                as_o[rg * HH + head] = ps;
                ad_o[rg * HH + head] = pd;
            }
        }
    }
}

// ---------------- warp-per-node pull-mode GAT aggregation ----------------
// One WARP per destination node (8 nodes per 256-thread block). Thread `lane`
// owns halves [lane*VH, lane*VH+VH) of the [H][C] feature row: one uint4 (C=64)
// or uint2 (C=32) gather per edge per thread. head = lane>>3 falls out of the
// layout. Head-mean via shfl_xor(8,16) — no smem, no barriers.
template <int C, bool HOUT>
__global__ void __launch_bounds__(256) gat_aggregate_kernel(
        const int* __restrict__ rowptr,
        const int* __restrict__ csr_src,
        const float* __restrict__ as_i,
        const float* __restrict__ ad_i,
        const __half* __restrict__ feat,    // [N, HH*C] halves
        const float* __restrict__ bias,
        void* __restrict__ outp, int do_relu) {
    constexpr int VH = HH * C / 32;         // halves per thread: 8 (C=64), 4 (C=32)
    const int lane = threadIdx.x & 31;
    const int warp = threadIdx.x >> 5;
    const int node = blockIdx.x * 8 + warp;
    if (node >= NN) return;
    const int head = lane >> 3;
    const float adh = __ldg(&ad_i[node * HH + head]);
    int beg = __ldg(&rowptr[node]), end = __ldg(&rowptr[node + 1]);

    float acc[VH];
#pragma unroll
    for (int j = 0; j < VH; j++) acc[j] = 0.f;
    float denom = 0.f;

    int e = beg;
    for (; e + 4 <= end; e += 4) {
        int s[4]; float a[4];
        uint4 u4[4]; uint2 u2[4];
#pragma unroll
        for (int q = 0; q < 4; q++) s[q] = __ldg(&csr_src[e + q]);
#pragma unroll
        for (int q = 0; q < 4; q++) {
            if (VH == 8) u4[q] = ((const uint4*)(feat + (size_t)s[q] * HH * C))[lane];
            else         u2[q] = ((const uint2*)(feat + (size_t)s[q] * HH * C))[lane];
        }
#pragma unroll
        for (int q = 0; q < 4; q++) a[q] = __ldg(&as_i[s[q] * HH + head]);
#pragma unroll
        for (int q = 0; q < 4; q++) {
            float eq = a[q] + adh; eq = eq > 0.f ? eq : NEG_SLOPE * eq;
            float xq = __expf(eq);
            denom += xq;
            const __half2* hp = (VH == 8) ? (const __half2*)&u4[q] : (const __half2*)&u2[q];
#pragma unroll
            for (int j = 0; j < VH / 2; j++) {
                float2 uf = __half22float2(hp[j]);
                acc[2 * j]     += xq * uf.x;
                acc[2 * j + 1] += xq * uf.y;
            }
        }
    }
    for (; e < end; e++) {
        int s0 = __ldg(&csr_src[e]);
        float a0 = __ldg(&as_i[s0 * HH + head]);
        uint4 u4; uint2 u2;
        if (VH == 8) u4 = ((const uint4*)(feat + (size_t)s0 * HH * C))[lane];
        else         u2 = ((const uint2*)(feat + (size_t)s0 * HH * C))[lane];
        float e0 = a0 + adh; e0 = e0 > 0.f ? e0 : NEG_SLOPE * e0;
        float x0 = __expf(e0);
        denom += x0;
        const __half2* hp = (VH == 8) ? (const __half2*)&u4 : (const __half2*)&u2;
#pragma unroll
        for (int j = 0; j < VH / 2; j++) {
            float2 uf = __half22float2(hp[j]);
            acc[2 * j]     += x0 * uf.x;
            acc[2 * j + 1] += x0 * uf.y;
        }
    }

    // alpha normalization (per-head denom), then head-sum butterfly
    float inv = 1.f / (denom + EPSV);
#pragma unroll
    for (int j = 0; j < VH; j++) {
        acc[j] *= inv;
        acc[j] += __shfl_xor_sync(0xffffffffu, acc[j], 8);
        acc[j] += __shfl_xor_sync(0xffffffffu, acc[j], 16);
    }

    if (lane < 8) {
        int c0 = lane * VH;            // output channels [c0, c0+VH)
        float v[VH];
#pragma unroll
        for (int j = 0; j < VH; j++) {
            v[j] = acc[j] * 0.25f + __ldg(&bias[c0 + j]);
            if (do_relu) v[j] = fmaxf(v[j], 0.f);
        }
        if (HOUT) {
            __half* op = (__half*)outp + (size_t)node * C + c0;
#pragma unroll
            for (int j = 0; j < VH / 2; j++)
                ((__half2*)op)[j] = __float22half2_rn(make_float2(v[2 * j], v[2 * j + 1]));
        } else {
            float* op = (float*)outp + (size_t)node * C + c0;
#pragma unroll
            for (int j = 0; j < VH; j++) op[j] = v[j];
        }
    }
}

// ---------------- host launcher ----------------
extern "C" void kernel_launch(void* const* d_in, const int* in_sizes, int n_in,
                              void* d_out, int out_size) {
    const float* x   = (const float*)d_in[0];
    const void*  ei  = d_in[1];
    const float* W1  = (const float*)d_in[2];
    const float* as1 = (const float*)d_in[3];
    const float* ad1 = (const float*)d_in[4];
    const float* b1  = (const float*)d_in[5];
    const float* W2  = (const float*)d_in[6];
    const float* as2 = (const float*)d_in[7];
    const float* ad2 = (const float*)d_in[8];
    const float* b2  = (const float*)d_in[9];
    float* out = (float*)d_out;

    __half *feat, *hmid;
    float *asb, *adb;
    int *deg, *rowptr, *cursor, *csr, *partial;
    cudaGetSymbolAddress((void**)&feat,    g_feat);
    cudaGetSymbolAddress((void**)&hmid,    g_hmid);
    cudaGetSymbolAddress((void**)&asb,     g_as);
    cudaGetSymbolAddress((void**)&adb,     g_ad);
    cudaGetSymbolAddress((void**)&deg,     g_deg);
    cudaGetSymbolAddress((void**)&rowptr,  g_rowptr);
    cudaGetSymbolAddress((void**)&cursor,  g_cursor);
    cudaGetSymbolAddress((void**)&csr,     g_csr_src);
    cudaGetSymbolAddress((void**)&partial, g_partial);

    // One-time resources (created on first, uncaptured correctness call; reused
    // in graph capture — same work every call, fully deterministic).
    static cudaStream_t sCsr = nullptr;
    static cudaEvent_t evFork = nullptr, evCsr = nullptr;
    if (!sCsr) {
        cudaStreamCreateWithFlags(&sCsr, cudaStreamNonBlocking);
        cudaEventCreateWithFlags(&evFork, cudaEventDisableTiming);
        cudaEventCreateWithFlags(&evCsr, cudaEventDisableTiming);
    }

    const int rowBlocks = (NN + 127) / 128;   // 391
    const int aggBlocks = (NN + 7) / 8;       // 6250

    // ---- fork: GEMM1 on main stream, CSR build on sCsr ----
    cudaEventRecord(evFork, 0);
    cudaStreamWaitEvent(sCsr, evFork, 0);

    // Main branch: GEMM1 (fp32 x / W1 converted in-kernel)
    gemm_mma_kernel<FIN, CC1, false><<<dim3(HH * CC1 / 64, rowBlocks), 256>>>(
        x, W1, feat, NN, as1, ad1, asb, adb);

    // CSR branch (independent of features/weights)
    cudaMemsetAsync(deg, 0, NN * sizeof(int), sCsr);
    hist_kernel<<<1024, 256, 0, sCsr>>>(ei, deg);
    scan_partials_kernel<<<NB, SCAN_CHUNK, 0, sCsr>>>(deg, partial);
    scan_final_kernel<<<NB, SCAN_CHUNK, 0, sCsr>>>(deg, partial, rowptr, cursor);
    fill_csr_kernel<<<512, 256, 0, sCsr>>>(ei, cursor, csr);
    cudaEventRecord(evCsr, sCsr);

    // ---- join: aggregation needs both GEMM1 outputs and the CSR ----
    cudaStreamWaitEvent(0, evCsr, 0);

    gat_aggregate_kernel<CC1, true><<<aggBlocks, 256>>>(
        rowptr, csr, asb, adb, feat, b1, hmid, 1);

    // ---- layer 2 (A = fp16 hmid, B = fp32 W2 converted in-kernel) ----
    gemm_mma_kernel<CC1, CC2, true><<<dim3(HH * CC2 / 64, rowBlocks), 256>>>(
        hmid, W2, feat, NN, as2, ad2, asb, adb);
    gat_aggregate_kernel<CC2, false><<<aggBlocks, 256>>>(
        rowptr, csr, asb, adb, feat, b2, out, 0);
}